// round 12
// baseline (speedup 1.0000x reference)
#include <cuda_runtime.h>
#include <cuda_fp16.h>
#include <cstdint>

#define BH   16
#define NSEQ 4096
#define DIM  64
#define ROWS (BH * NSEQ)
#define ELEMS (ROWS * DIM)

// Scratch (__device__ globals per allocation-free rule)
__device__ __half g_qk[ELEMS];   // normalized x, fp16, [bh][n][d]
__device__ __half g_vt[ELEMS];   // x transposed,  fp16, [bh][d][n]
__device__ __half g_av[ELEMS];   // attention output (normalized), fp16
__device__ float  g_tmp[ELEMS];  // block-1 output y1

// ---------------------------------------------------------------------------
// helpers
// ---------------------------------------------------------------------------
__device__ __forceinline__ uint32_t smem_u32(const void* p) {
    uint32_t a;
    asm("{ .reg .u64 t; cvta.to.shared.u64 t, %1; cvt.u32.u64 %0, t; }" : "=r"(a) : "l"(p));
    return a;
}
__device__ __forceinline__ void sts32(uint32_t a, uint32_t v) {
    asm volatile("st.shared.b32 [%0], %1;" :: "r"(a), "r"(v));
}
__device__ __forceinline__ uint4 lds128u(uint32_t a) {
    uint4 v;
    asm volatile("ld.shared.v4.b32 {%0,%1,%2,%3}, [%4];"
                 : "=r"(v.x), "=r"(v.y), "=r"(v.z), "=r"(v.w) : "r"(a));
    return v;
}
__device__ __forceinline__ void ldsm_x4(uint32_t r[4], uint32_t addr) {
    asm volatile("ldmatrix.sync.aligned.m8n8.x4.shared.b16 {%0,%1,%2,%3}, [%4];"
                 : "=r"(r[0]), "=r"(r[1]), "=r"(r[2]), "=r"(r[3]) : "r"(addr));
}
__device__ __forceinline__ uint32_t packh(float lo, float hi) {
    uint32_t r;
    asm("cvt.rn.f16x2.f32 %0, %1, %2;" : "=r"(r) : "f"(hi), "f"(lo));
    return r;
}
__device__ __forceinline__ uint32_t hfma2(uint32_t a, uint32_t b, uint32_t c) {
    uint32_t d;
    asm("fma.rn.f16x2 %0, %1, %2, %3;" : "=r"(d) : "r"(a), "r"(b), "r"(c));
    return d;
}
__device__ __forceinline__ uint32_t hmul2(uint32_t a, uint32_t b) {
    uint32_t d;
    asm("mul.rn.f16x2 %0, %1, %2;" : "=r"(d) : "r"(a), "r"(b));
    return d;
}
__device__ __forceinline__ uint32_t ex2h2(uint32_t y) {
    uint32_t r;
    asm("ex2.approx.f16x2 %0, %1;" : "=r"(r) : "r"(y));
    return r;
}
// f16 inputs, f16 accumulate (2x rate)
__device__ __forceinline__ void mma_f16a(uint32_t c[2], const uint32_t a[4],
                                         uint32_t b0, uint32_t b1) {
    asm("mma.sync.aligned.m16n8k16.row.col.f16.f16.f16.f16 "
        "{%0,%1},{%2,%3,%4,%5},{%6,%7},{%0,%1};"
        : "+r"(c[0]), "+r"(c[1])
        : "r"(a[0]), "r"(a[1]), "r"(a[2]), "r"(a[3]), "r"(b0), "r"(b1));
}
// f16 inputs, f32 accumulate (l ones-block only)
__device__ __forceinline__ void mma_f32a(float c[4], const uint32_t a[4],
                                         uint32_t b0, uint32_t b1) {
    asm("mma.sync.aligned.m16n8k16.row.col.f32.f16.f16.f32 "
        "{%0,%1,%2,%3},{%4,%5,%6,%7},{%8,%9},{%0,%1,%2,%3};"
        : "+f"(c[0]), "+f"(c[1]), "+f"(c[2]), "+f"(c[3])
        : "r"(a[0]), "r"(a[1]), "r"(a[2]), "r"(a[3]), "r"(b0), "r"(b1));
}
#define CP_ASYNC16(dst, src) \
    asm volatile("cp.async.cg.shared.global [%0], [%1], 16;" :: "r"(dst), "l"(src))
#define CP_COMMIT() asm volatile("cp.async.commit_group;" ::: "memory")
#define CP_WAIT0()  asm volatile("cp.async.wait_group 0;" ::: "memory")

// ---------------------------------------------------------------------------
// prep (block 1 only): L2-normalize -> qn; transpose -> vt
// ---------------------------------------------------------------------------
__global__ void __launch_bounds__(256)
prep_kernel(const float* __restrict__ x,
            __half* __restrict__ qn, __half* __restrict__ vt) {
    __shared__ float tile[64][65];
    __shared__ float sinv[64];
    const int tid = threadIdx.x;
    const int bh = blockIdx.y;
    const int n0 = blockIdx.x * 64;
    const float* xb = x + ((size_t)bh * NSEQ + n0) * DIM;
    #pragma unroll
    for (int i = 0; i < 16; i++) {
        int idx = tid + i * 256;
        tile[idx >> 6][idx & 63] = xb[idx];
    }
    __syncthreads();
    {
        int n = tid >> 2, p = tid & 3;
        float ss = 0.0f;
        #pragma unroll
        for (int k = 0; k < 16; k++) {
            float v = tile[n][p * 16 + k];
            ss = fmaf(v, v, ss);
        }
        ss += __shfl_xor_sync(0xFFFFFFFFu, ss, 1);
        ss += __shfl_xor_sync(0xFFFFFFFFu, ss, 2);
        if (p == 0) sinv[n] = 1.0f / fmaxf(sqrtf(ss), 1e-12f);
    }
    __syncthreads();
    __half* qb = qn + ((size_t)bh * NSEQ + n0) * DIM;
    __half* vb = vt + (size_t)bh * NSEQ * DIM + n0;
    #pragma unroll
    for (int i = 0; i < 16; i++) {
        int idx = tid + i * 256;
        int n = idx >> 6, d = idx & 63;
        qb[idx] = __float2half(tile[n][d] * sinv[n]);
    }
    #pragma unroll
    for (int i = 0; i < 16; i++) {
        int idx = tid + i * 256;
        int d = idx >> 6, n = idx & 63;
        vb[(size_t)d * NSEQ + n] = __float2half(tile[n][d]);
    }
}

// ---------------------------------------------------------------------------
// attention mainloop only -> writes normalized av (f16) to global scratch.
// 4 warps, 32 q rows/warp, __launch_bounds__(128,4): 512 CTAs in ONE wave.
// S f16-accum; O data blocks f16-accum; l ones-block f32-accum.
// aP halved to [2][2][4] via key-phase split (S b0..3 -> O(f0); S b4..7 -> O(f1)).
// ---------------------------------------------------------------------------
#define KV_ROWB 144
#define KT_BYTES (64 * KV_ROWB)         // 9216
#define VT_BYTES (72 * KV_ROWB)         // 10368 (64 data + ones + zeros)
#define BUF_BYTES (KT_BYTES + VT_BYTES) // 19584
#define AV_STRIDE 36                     // u32 per row (144 B, 16-aligned)

// S block b (phase-local slot jj = (b>>1)&1)
#define S_BLOCK(b)                                                            \
    {                                                                         \
        uint32_t kb = smK + (uint32_t)(b) * (8 * KV_ROWB) + lrow + kseg;      \
        uint32_t f0[4], f1[4];                                                \
        ldsm_x4(f0, kb);                                                      \
        ldsm_x4(f1, kb + 64);                                                 \
        _Pragma("unroll")                                                     \
        for (int rg = 0; rg < 2; rg++) {                                      \
            uint32_t s[2];                                                    \
            s[0] = 0u; s[1] = 0u;                                             \
            mma_f16a(s, aQ[rg][0], f0[0], f0[1]);                             \
            mma_f16a(s, aQ[rg][1], f0[2], f0[3]);                             \
            mma_f16a(s, aQ[rg][2], f1[0], f1[1]);                             \
            mma_f16a(s, aQ[rg][3], f1[2], f1[3]);                             \
            uint32_t pa = ex2h2(hfma2(s[0], cc, ncc));                        \
            uint32_t pb = ex2h2(hfma2(s[1], cc, ncc));                        \
            int jj = ((b) >> 1) & 1;                                          \
            if (((b) & 1) == 0) { aP[rg][jj][0] = pa; aP[rg][jj][1] = pb; }   \
            else                { aP[rg][jj][2] = pa; aP[rg][jj][3] = pb; }   \
        }                                                                     \
    }

__global__ void __launch_bounds__(128, 4)
attn_mma_kernel(const __half* __restrict__ qk,
                const __half* __restrict__ vt,
                const float* __restrict__ alpha_p,
                __half* __restrict__ av_out) {
    __shared__ __align__(16) uint8_t smem_raw[2 * BUF_BYTES];

    const int tid  = threadIdx.x;
    const int warp = tid >> 5;
    const int lane = tid & 31;
    const int lr   = lane >> 2;
    const int lc   = lane & 3;
    const uint32_t smbase = smem_u32(smem_raw);

    const size_t base = (size_t)blockIdx.y * NSEQ * DIM;
    const int q0 = blockIdx.x * 128 + warp * 32;
    const float cf = 1.4426950408889634f / fmaxf(alpha_p[0], 0.01f);
    const uint32_t cc  = packh(cf, cf);
    const uint32_t ncc = packh(-cf, -cf);

    // ---- Q A-fragments: 2 row-groups x 4 k-chunks ----
    uint32_t aQ[2][4][4];
    #pragma unroll
    for (int rg = 0; rg < 2; rg++) {
        const __half* qr0 = qk + base + (size_t)(q0 + rg * 16 + lr) * DIM;
        const __half* qr1 = qr0 + 8 * DIM;
        #pragma unroll
        for (int j = 0; j < 4; j++) {
            aQ[rg][j][0] = *(const uint32_t*)(qr0 + 16 * j + 2 * lc);
            aQ[rg][j][1] = *(const uint32_t*)(qr1 + 16 * j + 2 * lc);
            aQ[rg][j][2] = *(const uint32_t*)(qr0 + 16 * j + 8 + 2 * lc);
            aQ[rg][j][3] = *(const uint32_t*)(qr1 + 16 * j + 8 + 2 * lc);
        }
    }

    const __half* gK  = qk + base;
    const __half* gVt = vt + base;

    // ---- init ones/zero rows (V rows 64..71) in BOTH buffers ----
    #pragma unroll
    for (int i = 0; i < 3; i++) {
        int idx = tid + i * 128;
        if (idx < 288) {
            uint32_t v = (idx < 36) ? 0x3C003C00u : 0u;   // row 64 = 1.0 fp16
            sts32(smbase + KT_BYTES + 64 * KV_ROWB + idx * 4, v);
            sts32(smbase + BUF_BYTES + KT_BYTES + 64 * KV_ROWB + idx * 4, v);
        }
    }

    // ---- stage tile 0 ----
    #pragma unroll
    for (int i = 0; i < 4; i++) {
        int id = tid + i * 128;
        int n = id >> 3, cseg = id & 7;
        CP_ASYNC16(smbase + n * KV_ROWB + cseg * 16, gK + n * DIM + cseg * 8);
        CP_ASYNC16(smbase + KT_BYTES + n * KV_ROWB + cseg * 16,
                   gVt + (size_t)n * NSEQ + cseg * 8);
    }
    CP_COMMIT();

    uint32_t o16[2][8][2];      // f16x2 O accumulators
    float    ol[2][4];          // f32 l accumulators (ones block)
    #pragma unroll
    for (int rg = 0; rg < 2; rg++) {
        #pragma unroll
        for (int b = 0; b < 8; b++) { o16[rg][b][0] = 0u; o16[rg][b][1] = 0u; }
        #pragma unroll
        for (int k = 0; k < 4; k++) ol[rg][k] = 0.0f;
    }

    const uint32_t lrow = (uint32_t)(lane & 7) * KV_ROWB;
    const uint32_t kseg = (uint32_t)(lane >> 3) * 16;

    for (int it = 0; it < NSEQ / 64; ++it) {
        CP_WAIT0();
        __syncthreads();
        const uint32_t smK = smbase + (uint32_t)(it & 1) * BUF_BYTES;
        const uint32_t smV = smK + KT_BYTES;

        if (it + 1 < NSEQ / 64) {
            const __half* nK  = gK  + (it + 1) * 64 * DIM;
            const __half* nVt = gVt + (it + 1) * 64;
            uint32_t dbuf = smbase + (uint32_t)((it + 1) & 1) * BUF_BYTES;
            #pragma unroll
            for (int i = 0; i < 4; i++) {
                int id = tid + i * 128;
                int n = id >> 3, cseg = id & 7;
                CP_ASYNC16(dbuf + n * KV_ROWB + cseg * 16, nK + n * DIM + cseg * 8);
                CP_ASYNC16(dbuf + KT_BYTES + n * KV_ROWB + cseg * 16,
                           nVt + (size_t)n * NSEQ + cseg * 8);
            }
            CP_COMMIT();
        }

        uint32_t aP[2][2][4];

        // ===== phase A: keys 0..31 =====
        #pragma unroll
        for (int b = 0; b < 4; b++) S_BLOCK(b)
        #pragma unroll
        for (int b = 0; b < 9; b++) {
            uint32_t vb = smV + (uint32_t)b * (8 * KV_ROWB) + lrow + kseg;
            uint32_t f[4];
            ldsm_x4(f, vb);
            if (b < 8) {
                #pragma unroll
                for (int rg = 0; rg < 2; rg++) {
                    mma_f16a(o16[rg][b], aP[rg][0], f[0], f[1]);
                    mma_f16a(o16[rg][b], aP[rg][1], f[2], f[3]);
                }
            } else {
                #pragma unroll
                for (int rg = 0; rg < 2; rg++) {
                    mma_f32a(ol[rg], aP[rg][0], f[0], f[1]);
                    mma_f32a(ol[rg], aP[rg][1], f[2], f[3]);
                }
            }
        }

        // ===== phase B: keys 32..63 =====
        #pragma unroll
        for (int b = 4; b < 8; b++) S_BLOCK(b)
        #pragma unroll
        for (int b = 0; b < 9; b++) {
            uint32_t vb = smV + (uint32_t)b * (8 * KV_ROWB) + lrow + kseg + 64;
            uint32_t f[4];
            ldsm_x4(f, vb);
            if (b < 8) {
                #pragma unroll
                for (int rg = 0; rg < 2; rg++) {
                    mma_f16a(o16[rg][b], aP[rg][0], f[0], f[1]);
                    mma_f16a(o16[rg][b], aP[rg][1], f[2], f[3]);
                }
            } else {
                #pragma unroll
                for (int rg = 0; rg < 2; rg++) {
                    mma_f32a(ol[rg], aP[rg][0], f[0], f[1]);
                    mma_f32a(ol[rg], aP[rg][1], f[2], f[3]);
                }
            }
        }
    }

    __syncthreads();   // all warps done with K/V smem

    // ---- normalize by l (f32, ones col 64 -> lc==0 regs 0/2), av -> smem ----
    #pragma unroll
    for (int rg = 0; rg < 2; rg++) {
        const float lA = __shfl_sync(0xFFFFFFFFu, ol[rg][0], lane & ~3);
        const float lB = __shfl_sync(0xFFFFFFFFu, ol[rg][2], lane & ~3);
        const float i0f = 1.0f / lA;
        const float i1f = 1.0f / lB;
        const uint32_t i0 = packh(i0f, i0f);
        const uint32_t i1 = packh(i1f, i1f);
        int row0 = warp * 32 + rg * 16 + lr;
        uint32_t a0 = smbase + (uint32_t)(row0 * AV_STRIDE + lc) * 4;
        uint32_t a1 = smbase + (uint32_t)((row0 + 8) * AV_STRIDE + lc) * 4;
        #pragma unroll
        for (int b = 0; b < 8; b++) {
            sts32(a0 + b * 16, hmul2(o16[rg][b][0], i0));
            sts32(a1 + b * 16, hmul2(o16[rg][b][1], i1));
        }
    }
    __syncthreads();

    // ---- coalesced copy av -> global (f16 [row][d]) ----
    {
        uint4* dst = (uint4*)(av_out + base + (size_t)blockIdx.x * 128 * DIM);
        #pragma unroll
        for (int i = 0; i < 8; i++) {
            int idx4 = tid + i * 128;            // 1024 uint4 total
            int row = idx4 >> 3, cseg = idx4 & 7;
            uint4 v = lds128u(smbase + (uint32_t)row * (AV_STRIDE * 4) + cseg * 16);
            dst[idx4] = v;
        }
    }
}

// ---------------------------------------------------------------------------
// fused epilogue + prep: y = relu(av @ W^T + x); write y, qn(y), vt(y)
// 256 threads, 64 rows/CTA.
// ---------------------------------------------------------------------------
__global__ void __launch_bounds__(256)
epiprep_kernel(const __half* __restrict__ av, const float* __restrict__ W,
               const float* __restrict__ x, float* __restrict__ y,
               __half* __restrict__ qn, __half* __restrict__ vt) {
    __shared__ float wsm[64 * 64];
    __shared__ float tile[64][65];
    __shared__ __half avs[64 * 64];
    __shared__ float sinv[64];
    const int tid = threadIdx.x;
    const int bh = blockIdx.y;
    const int n0 = blockIdx.x * 64;
    const size_t rbase = (size_t)bh * NSEQ + n0;

    #pragma unroll
    for (int i = 0; i < 4; i++)
        ((float4*)wsm)[tid + i * 256] = ((const float4*)W)[tid + i * 256];
    {
        const uint4* avb = (const uint4*)(av + rbase * DIM);
        #pragma unroll
        for (int i = 0; i < 2; i++)
            ((uint4*)avs)[tid + i * 256] = avb[tid + i * 256];
    }
    __syncthreads();

    const int row = tid >> 2, q = tid & 3;
    float avf[64];
    {
        const __half2* ar = (const __half2*)(avs + row * 64);
        #pragma unroll
        for (int i = 0; i < 32; i++) {
            float2 f = __half22float2(ar[i]);
            avf[2 * i] = f.x; avf[2 * i + 1] = f.y;
        }
    }
    const float4* xr4 = (const float4*)(x + (rbase + row) * DIM) + q * 4;
    float4* yr4 = (float4*)(y + (rbase + row) * DIM) + q * 4;
    #pragma unroll
    for (int eb = 0; eb < 4; eb++) {
        float r[4];
        #pragma unroll
        for (int k = 0; k < 4; k++) {
            int e = q * 16 + eb * 4 + k;
            const float* wr = wsm + e * 64;
            float4 acc = make_float4(0.f, 0.f, 0.f, 0.f);
            #pragma unroll
            for (int i = 0; i < 16; i++) {
                float4 wv = ((const float4*)wr)[i];
                acc.x = fmaf(avf[4 * i + 0], wv.x, acc.x);
                acc.y = fmaf(avf[4 * i + 1], wv.y, acc.y);
                acc.z = fmaf(avf[4 * i + 2], wv.z, acc.z);
                acc.w = fmaf(avf[4 * i + 3], wv.w, acc.w);
            }
            r[k] = (acc.x + acc.y) + (acc.z + acc.w);
        }
        float4 xr = xr4[eb];
        float4 res;
        res.x = fmaxf(r[0] + xr.x, 0.0f);
        res.y = fmaxf(r[1] + xr.y, 0.0f);
        res.z = fmaxf(r[2] + xr.z, 0.0f);
        res.w = fmaxf(r[3] + xr.w, 0.0f);
        yr4[eb] = res;
        int e0 = q * 16 + eb * 4;
        tile[row][e0]     = res.x;
        tile[row][e0 + 1] = res.y;
        tile[row][e0 + 2] = res.z;
        tile[row][e0 + 3] = res.w;
    }
    __syncthreads();

    // prep on y
    {
        int n = tid >> 2, p = tid & 3;
        float ss = 0.0f;
        #pragma unroll
        for (int k = 0; k < 16; k++) {
            float v = tile[n][p * 16 + k];
            ss = fmaf(v, v, ss);
        }
        ss += __shfl_xor_sync(0xFFFFFFFFu, ss, 1);
        ss += __shfl_xor_sync(0xFFFFFFFFu, ss, 2);
        if (p == 0) sinv[n] = 1.0f / fmaxf(sqrtf(ss), 1e-12f);
    }
    __syncthreads();
    __half* qb = qn + rbase * DIM;
    __half* vb = vt + (size_t)bh * NSEQ * DIM + n0;
    #pragma unroll
    for (int i = 0; i < 16; i++) {
        int idx = tid + i * 256;
        int n = idx >> 6, d = idx & 63;
        qb[idx] = __float2half(tile[n][d] * sinv[n]);
    }
    #pragma unroll
    for (int i = 0; i < 16; i++) {
        int idx = tid + i * 256;
        int d = idx >> 6, n = idx & 63;
        vb[(size_t)d * NSEQ + n] = __float2half(tile[n][d]);
    }
}

// ---------------------------------------------------------------------------
// final epilogue: out = relu(av @ W^T + x)
// ---------------------------------------------------------------------------
__global__ void __launch_bounds__(256)
epi_kernel(const __half* __restrict__ av, const float* __restrict__ W,
           const float* __restrict__ x, float* __restrict__ out) {
    __shared__ float wsm[64 * 64];
    __shared__ __half avs[64 * 64];
    const int tid = threadIdx.x;
    const size_t rbase = (size_t)blockIdx.y * NSEQ + blockIdx.x * 64;

    #pragma unroll
    for (int i = 0; i < 4; i++)
        ((float4*)wsm)[tid + i * 256] = ((const float4*)W)[tid + i * 256];
    {
        const uint4* avb = (const uint4*)(av + rbase * DIM);
        #pragma unroll
        for (int i = 0; i < 2; i++)
            ((uint4*)avs)[tid + i * 256] = avb[tid + i * 256];
    }
    __syncthreads();

    const int row = tid >> 2, q = tid & 3;
    float avf[64];
    {
        const __half2* ar = (const __half2*)(avs + row * 64);
        #pragma unroll
        for (int i = 0; i < 32; i++) {
            float2 f = __half22float2(ar[i]);
            avf[2 * i] = f.x; avf[2 * i + 1] = f.y;
        }
    }
    const float4* xr4 = (const float4*)(x + (rbase + row) * DIM) + q * 4;
    float4* or4 = (float4*)(out + (rbase + row) * DIM) + q * 4;
    #pragma unroll
    for (int eb = 0; eb < 4; eb++) {
        float r[4];
        #pragma unroll
        for (int k = 0; k < 4; k++) {
            int e = q * 16 + eb * 4 + k;
            const float* wr = wsm + e * 64;
            float4 acc = make_float4(0.f, 0.f, 0.f, 0.f);
            #pragma unroll
            for (int i = 0; i < 16; i++) {
                float4 wv = ((const float4*)wr)[i];
                acc.x = fmaf(avf[4 * i + 0], wv.x, acc.x);
                acc.y = fmaf(avf[4 * i + 1], wv.y, acc.y);
                acc.z = fmaf(avf[4 * i + 2], wv.z, acc.z);
                acc.w = fmaf(avf[4 * i + 3], wv.w, acc.w);
            }
            r[k] = (acc.x + acc.y) + (acc.z + acc.w);
        }
        float4 xr = xr4[eb];
        float4 res;
        res.x = fmaxf(r[0] + xr.x, 0.0f);
        res.y = fmaxf(r[1] + xr.y, 0.0f);
        res.z = fmaxf(r[2] + xr.z, 0.0f);
        res.w = fmaxf(r[3] + xr.w, 0.0f);
        or4[eb] = res;
    }
}

// ---------------------------------------------------------------------------
// Driver (graph-capturable)
// ---------------------------------------------------------------------------
extern "C" void kernel_launch(void* const* d_in, const int* in_sizes, int n_in,
                              void* d_out, int out_size) {
    const float* x      = (const float*)d_in[0];
    const float* W1     = (const float*)d_in[1];
    const float* W2     = (const float*)d_in[2];
    const float* alpha1 = (const float*)d_in[3];
    const float* alpha2 = (const float*)d_in[4];
    float* out = (float*)d_out;

    __half* qk;  cudaGetSymbolAddress((void**)&qk,  g_qk);
    __half* vtp; cudaGetSymbolAddress((void**)&vtp, g_vt);
    __half* avp; cudaGetSymbolAddress((void**)&avp, g_av);
    float* tmp;  cudaGetSymbolAddress((void**)&tmp, g_tmp);

    dim3 pgrid(NSEQ / 64, BH);
    dim3 agrid(NSEQ / 128, BH);

    prep_kernel<<<pgrid, 256>>>(x, qk, vtp);
    attn_mma_kernel<<<agrid, 128>>>(qk, vtp, alpha1, avp);
    epiprep_kernel<<<pgrid, 256>>>(avp, W1, x, tmp, qk, vtp);
    attn_mma_kernel<<<agrid, 128>>>(qk, vtp, alpha2, avp);
    epi_kernel<<<pgrid, 256>>>(avp, W2, tmp, out);
}

// round 13
// speedup vs baseline: 1.6078x; 1.6078x over previous
#include <cuda_runtime.h>
#include <cuda_fp16.h>
#include <cstdint>

#define BH   16
#define NSEQ 4096
#define DIM  64
#define ROWS (BH * NSEQ)
#define ELEMS (ROWS * DIM)

// Scratch (__device__ globals per allocation-free rule)
__device__ __half g_qk1[ELEMS];
__device__ __half g_vt1[ELEMS];
__device__ __half g_qk2[ELEMS];
__device__ __half g_vt2[ELEMS];
__device__ float  g_tmp[ELEMS];

// ---------------------------------------------------------------------------
// helpers
// ---------------------------------------------------------------------------
__device__ __forceinline__ uint32_t smem_u32(const void* p) {
    uint32_t a;
    asm("{ .reg .u64 t; cvta.to.shared.u64 t, %1; cvt.u32.u64 %0, t; }" : "=r"(a) : "l"(p));
    return a;
}
__device__ __forceinline__ void sts32(uint32_t a, uint32_t v) {
    asm volatile("st.shared.b32 [%0], %1;" :: "r"(a), "r"(v));
}
__device__ __forceinline__ void ldsm_x4(uint32_t r[4], uint32_t addr) {
    asm volatile("ldmatrix.sync.aligned.m8n8.x4.shared.b16 {%0,%1,%2,%3}, [%4];"
                 : "=r"(r[0]), "=r"(r[1]), "=r"(r[2]), "=r"(r[3]) : "r"(addr));
}
__device__ __forceinline__ uint32_t packh(float lo, float hi) {
    uint32_t r;
    asm("cvt.rn.f16x2.f32 %0, %1, %2;" : "=r"(r) : "f"(hi), "f"(lo));
    return r;
}
__device__ __forceinline__ uint32_t hfma2(uint32_t a, uint32_t b, uint32_t c) {
    uint32_t d;
    asm("fma.rn.f16x2 %0, %1, %2, %3;" : "=r"(d) : "r"(a), "r"(b), "r"(c));
    return d;
}
__device__ __forceinline__ uint32_t hadd2(uint32_t a, uint32_t b) {
    uint32_t d;
    asm("add.rn.f16x2 %0, %1, %2;" : "=r"(d) : "r"(a), "r"(b));
    return d;
}
__device__ __forceinline__ uint32_t hmul2(uint32_t a, uint32_t b) {
    uint32_t d;
    asm("mul.rn.f16x2 %0, %1, %2;" : "=r"(d) : "r"(a), "r"(b));
    return d;
}
__device__ __forceinline__ uint32_t ex2h2(uint32_t y) {
    uint32_t r;
    asm("ex2.approx.f16x2 %0, %1;" : "=r"(r) : "r"(y));
    return r;
}
__device__ __forceinline__ float2 h2f2(uint32_t u) {
    __half2 h = *reinterpret_cast<__half2*>(&u);
    return __half22float2(h);
}
// f16 in, f16 accumulate (2x rate)
__device__ __forceinline__ void mma_f16a(uint32_t c[2], const uint32_t a[4],
                                         uint32_t b0, uint32_t b1) {
    asm("mma.sync.aligned.m16n8k16.row.col.f16.f16.f16.f16 "
        "{%0,%1},{%2,%3,%4,%5},{%6,%7},{%0,%1};"
        : "+r"(c[0]), "+r"(c[1])
        : "r"(a[0]), "r"(a[1]), "r"(a[2]), "r"(a[3]), "r"(b0), "r"(b1));
}
#define CP_ASYNC16(dst, src) \
    asm volatile("cp.async.cg.shared.global [%0], [%1], 16;" :: "r"(dst), "l"(src))
#define CP_COMMIT() asm volatile("cp.async.commit_group;" ::: "memory")
#define CP_WAIT0()  asm volatile("cp.async.wait_group 0;" ::: "memory")

// ---------------------------------------------------------------------------
// prep (block 1 only): L2-normalize -> qn; transpose -> vt
// ---------------------------------------------------------------------------
__global__ void __launch_bounds__(256)
prep_kernel(const float* __restrict__ x,
            __half* __restrict__ qn, __half* __restrict__ vt) {
    __shared__ float tile[64][65];
    __shared__ float sinv[64];
    const int tid = threadIdx.x;
    const int bh = blockIdx.y;
    const int n0 = blockIdx.x * 64;
    const float* xb = x + ((size_t)bh * NSEQ + n0) * DIM;
    #pragma unroll
    for (int i = 0; i < 16; i++) {
        int idx = tid + i * 256;
        tile[idx >> 6][idx & 63] = xb[idx];
    }
    __syncthreads();
    {
        int n = tid >> 2, p = tid & 3;
        float ss = 0.0f;
        #pragma unroll
        for (int k = 0; k < 16; k++) {
            float v = tile[n][p * 16 + k];
            ss = fmaf(v, v, ss);
        }
        ss += __shfl_xor_sync(0xFFFFFFFFu, ss, 1);
        ss += __shfl_xor_sync(0xFFFFFFFFu, ss, 2);
        if (p == 0) sinv[n] = 1.0f / fmaxf(sqrtf(ss), 1e-12f);
    }
    __syncthreads();
    __half* qb = qn + ((size_t)bh * NSEQ + n0) * DIM;
    __half* vb = vt + (size_t)bh * NSEQ * DIM + n0;
    #pragma unroll
    for (int i = 0; i < 16; i++) {
        int idx = tid + i * 256;
        int n = idx >> 6, d = idx & 63;
        qb[idx] = __float2half(tile[n][d] * sinv[n]);
    }
    #pragma unroll
    for (int i = 0; i < 16; i++) {
        int idx = tid + i * 256;
        int d = idx >> 6, n = idx & 63;
        vb[(size_t)d * NSEQ + n] = __float2half(tile[n][d]);
    }
}

// ---------------------------------------------------------------------------
// Fused attention block: mainloop (S f16a, O f16a, l via hadd2) + tensor-core
// epilogue (y = relu(av@W^T + x)) using the C->A fragment identity on o16.
// PREP=1 additionally L2-normalizes y and writes qn/vt for the next block.
// 4 warps, 32 q rows/warp, __launch_bounds__(128,4): single wave (512 CTAs).
// ---------------------------------------------------------------------------
#define KV_ROWB 144
#define KT_BYTES (64 * KV_ROWB)         // 9216
#define VT_BYTES (64 * KV_ROWB)         // 9216
#define BUF_BYTES (KT_BYTES + VT_BYTES) // 18432
#define TILE_STRIDE 66                   // f32 per row in epilogue tile
#define SINV_OFF (128 * TILE_STRIDE)     // float index of sinv array

// S block b (phase-local slot jj = (b>>1)&1)
#define S_BLOCK(b)                                                            \
    {                                                                         \
        uint32_t kb = smK + (uint32_t)(b) * (8 * KV_ROWB) + lrow + kseg;      \
        uint32_t f0[4], f1[4];                                                \
        ldsm_x4(f0, kb);                                                      \
        ldsm_x4(f1, kb + 64);                                                 \
        _Pragma("unroll")                                                     \
        for (int rg = 0; rg < 2; rg++) {                                      \
            uint32_t s[2];                                                    \
            s[0] = 0u; s[1] = 0u;                                             \
            mma_f16a(s, aQ[rg][0], f0[0], f0[1]);                             \
            mma_f16a(s, aQ[rg][1], f0[2], f0[3]);                             \
            mma_f16a(s, aQ[rg][2], f1[0], f1[1]);                             \
            mma_f16a(s, aQ[rg][3], f1[2], f1[3]);                             \
            uint32_t pa = ex2h2(hfma2(s[0], cc, ncc));                        \
            uint32_t pb = ex2h2(hfma2(s[1], cc, ncc));                        \
            int jj = ((b) >> 1) & 1;                                          \
            if (((b) & 1) == 0) { aP[rg][jj][0] = pa; aP[rg][jj][1] = pb; }   \
            else                { aP[rg][jj][2] = pa; aP[rg][jj][3] = pb; }   \
        }                                                                     \
    }

// per-phase l accumulation from aP (f16x2 adds, promoted to f32)
#define L_ACCUM()                                                             \
    _Pragma("unroll")                                                         \
    for (int rg = 0; rg < 2; rg++) {                                          \
        uint32_t tA = hadd2(hadd2(aP[rg][0][0], aP[rg][0][2]),               \
                            hadd2(aP[rg][1][0], aP[rg][1][2]));              \
        uint32_t tB = hadd2(hadd2(aP[rg][0][1], aP[rg][0][3]),               \
                            hadd2(aP[rg][1][1], aP[rg][1][3]));              \
        float2 fA = h2f2(tA); lf[rg][0] += fA.x + fA.y;                      \
        float2 fB = h2f2(tB); lf[rg][1] += fB.x + fB.y;                      \
    }

// O accumulation for one phase (koff = 0 or 64)
#define O_PHASE(koff)                                                         \
    _Pragma("unroll")                                                         \
    for (int b = 0; b < 8; b++) {                                             \
        uint32_t vb = smV + (uint32_t)b * (8 * KV_ROWB) + lrow + kseg + (koff); \
        uint32_t f[4];                                                        \
        ldsm_x4(f, vb);                                                       \
        _Pragma("unroll")                                                     \
        for (int rg = 0; rg < 2; rg++) {                                      \
            mma_f16a(o16[rg][b], aP[rg][0], f[0], f[1]);                      \
            mma_f16a(o16[rg][b], aP[rg][1], f[2], f[3]);                      \
        }                                                                     \
    }

template <int PREP>
__global__ void __launch_bounds__(128, 4)
attn_fused_kernel(const __half* __restrict__ qk,
                  const __half* __restrict__ vt,
                  const float* __restrict__ W,
                  const float* __restrict__ alpha_p,
                  const float* __restrict__ xin,
                  float* __restrict__ yout,
                  __half* __restrict__ qn_out,
                  __half* __restrict__ vt_out) {
    __shared__ __align__(16) uint8_t smem_raw[2 * BUF_BYTES];

    const int tid  = threadIdx.x;
    const int warp = tid >> 5;
    const int lane = tid & 31;
    const int lr   = lane >> 2;
    const int lc   = lane & 3;
    const uint32_t smbase = smem_u32(smem_raw);

    const size_t base = (size_t)blockIdx.y * NSEQ * DIM;
    const int q0 = blockIdx.x * 128 + warp * 32;
    const float cf = 1.4426950408889634f / fmaxf(alpha_p[0], 0.01f);
    const uint32_t cc  = packh(cf, cf);
    const uint32_t ncc = packh(-cf, -cf);

    // ---- Q A-fragments ----
    uint32_t aQ[2][4][4];
    #pragma unroll
    for (int rg = 0; rg < 2; rg++) {
        const __half* qr0 = qk + base + (size_t)(q0 + rg * 16 + lr) * DIM;
        const __half* qr1 = qr0 + 8 * DIM;
        #pragma unroll
        for (int j = 0; j < 4; j++) {
            aQ[rg][j][0] = *(const uint32_t*)(qr0 + 16 * j + 2 * lc);
            aQ[rg][j][1] = *(const uint32_t*)(qr1 + 16 * j + 2 * lc);
            aQ[rg][j][2] = *(const uint32_t*)(qr0 + 16 * j + 8 + 2 * lc);
            aQ[rg][j][3] = *(const uint32_t*)(qr1 + 16 * j + 8 + 2 * lc);
        }
    }

    const __half* gK  = qk + base;
    const __half* gVt = vt + base;

    // ---- stage tile 0 ----
    #pragma unroll
    for (int i = 0; i < 4; i++) {
        int id = tid + i * 128;
        int n = id >> 3, cseg = id & 7;
        CP_ASYNC16(smbase + n * KV_ROWB + cseg * 16, gK + n * DIM + cseg * 8);
        CP_ASYNC16(smbase + KT_BYTES + n * KV_ROWB + cseg * 16,
                   gVt + (size_t)n * NSEQ + cseg * 8);
    }
    CP_COMMIT();

    uint32_t o16[2][8][2];
    float lf[2][2];
    #pragma unroll
    for (int rg = 0; rg < 2; rg++) {
        #pragma unroll
        for (int b = 0; b < 8; b++) { o16[rg][b][0] = 0u; o16[rg][b][1] = 0u; }
        lf[rg][0] = 0.0f; lf[rg][1] = 0.0f;
    }

    const uint32_t lrow = (uint32_t)(lane & 7) * KV_ROWB;
    const uint32_t kseg = (uint32_t)(lane >> 3) * 16;

    for (int it = 0; it < NSEQ / 64; ++it) {
        CP_WAIT0();
        __syncthreads();
        const uint32_t smK = smbase + (uint32_t)(it & 1) * BUF_BYTES;
        const uint32_t smV = smK + KT_BYTES;

        if (it + 1 < NSEQ / 64) {
            const __half* nK  = gK  + (it + 1) * 64 * DIM;
            const __half* nVt = gVt + (it + 1) * 64;
            uint32_t dbuf = smbase + (uint32_t)((it + 1) & 1) * BUF_BYTES;
            #pragma unroll
            for (int i = 0; i < 4; i++) {
                int id = tid + i * 128;
                int n = id >> 3, cseg = id & 7;
                CP_ASYNC16(dbuf + n * KV_ROWB + cseg * 16, nK + n * DIM + cseg * 8);
                CP_ASYNC16(dbuf + KT_BYTES + n * KV_ROWB + cseg * 16,
                           nVt + (size_t)n * NSEQ + cseg * 8);
            }
            CP_COMMIT();
        }

        uint32_t aP[2][2][4];
        // phase A: keys 0..31
        #pragma unroll
        for (int b = 0; b < 4; b++) S_BLOCK(b)
        L_ACCUM()
        O_PHASE(0)
        // phase B: keys 32..63
        #pragma unroll
        for (int b = 4; b < 8; b++) S_BLOCK(b)
        L_ACCUM()
        O_PHASE(64)
    }

    __syncthreads();   // mainloop done with K/V smem

    // ---- stage W (f32 -> f16) into smem rows of 144B ----
    {
        #pragma unroll
        for (int i = 0; i < 16; i++) {
            int idx = tid + i * 128;          // 2048 f16x2 words
            float2 wv = ((const float2*)W)[idx];
            sts32(smbase + (uint32_t)(idx >> 5) * KV_ROWB + (idx & 31) * 4,
                  packh(wv.x, wv.y));
        }
    }
    __syncthreads();

    // ---- normalize o16 by l (quad-reduced, fp32 -> f16x2 scale) ----
    #pragma unroll
    for (int rg = 0; rg < 2; rg++) {
        float lA = lf[rg][0], lB = lf[rg][1];
        lA += __shfl_xor_sync(0xFFFFFFFFu, lA, 1);
        lA += __shfl_xor_sync(0xFFFFFFFFu, lA, 2);
        lB += __shfl_xor_sync(0xFFFFFFFFu, lB, 1);
        lB += __shfl_xor_sync(0xFFFFFFFFu, lB, 2);
        const float i0f = 1.0f / lA;
        const float i1f = 1.0f / lB;
        const uint32_t i0 = packh(i0f, i0f);
        const uint32_t i1 = packh(i1f, i1f);
        #pragma unroll
        for (int b = 0; b < 8; b++) {
            o16[rg][b][0] = hmul2(o16[rg][b][0], i0);
            o16[rg][b][1] = hmul2(o16[rg][b][1], i1);
        }
    }

    // ---- y = av @ W^T via MMA (o16 C-frags ARE the A-frags) ----
    uint32_t yc[2][8][2];
    #pragma unroll
    for (int rg = 0; rg < 2; rg++)
        #pragma unroll
        for (int b = 0; b < 8; b++) { yc[rg][b][0] = 0u; yc[rg][b][1] = 0u; }
    #pragma unroll
    for (int b = 0; b < 8; b++) {
        uint32_t wb = smbase + (uint32_t)b * (8 * KV_ROWB) + lrow + kseg;
        uint32_t f0[4], f1[4];
        ldsm_x4(f0, wb);
        ldsm_x4(f1, wb + 64);
        #pragma unroll
        for (int rg = 0; rg < 2; rg++) {
            uint32_t a0[4] = {o16[rg][0][0], o16[rg][0][1], o16[rg][1][0], o16[rg][1][1]};
            uint32_t a1[4] = {o16[rg][2][0], o16[rg][2][1], o16[rg][3][0], o16[rg][3][1]};
            uint32_t a2[4] = {o16[rg][4][0], o16[rg][4][1], o16[rg][5][0], o16[rg][5][1]};
            uint32_t a3[4] = {o16[rg][6][0], o16[rg][6][1], o16[rg][7][0], o16[rg][7][1]};
            mma_f16a(yc[rg][b], a0, f0[0], f0[1]);
            mma_f16a(yc[rg][b], a1, f0[2], f0[3]);
            mma_f16a(yc[rg][b], a2, f1[0], f1[1]);
            mma_f16a(yc[rg][b], a3, f1[2], f1[3]);
        }
    }
    __syncthreads();   // all warps done reading W before tile overwrites

    if (PREP == 0) {
        // ---- residual + relu, direct store ----
        #pragma unroll
        for (int rg = 0; rg < 2; rg++) {
            const int r0 = q0 + rg * 16 + lr;
            #pragma unroll
            for (int b = 0; b < 8; b++) {
                const int col = 8 * b + 2 * lc;
                float2 y0 = h2f2(yc[rg][b][0]);
                float2 y1 = h2f2(yc[rg][b][1]);
                float2 x0 = *(const float2*)(xin + base + (size_t)r0 * DIM + col);
                float2 x1 = *(const float2*)(xin + base + (size_t)(r0 + 8) * DIM + col);
                float2 o0, o1;
                o0.x = fmaxf(y0.x + x0.x, 0.0f); o0.y = fmaxf(y0.y + x0.y, 0.0f);
                o1.x = fmaxf(y1.x + x1.x, 0.0f); o1.y = fmaxf(y1.y + x1.y, 0.0f);
                *(float2*)(yout + base + (size_t)r0 * DIM + col) = o0;
                *(float2*)(yout + base + (size_t)(r0 + 8) * DIM + col) = o1;
            }
        }
    } else {
        // ---- residual + relu into smem tile; row norms; write y/qn/vt ----
        float* tptr = (float*)smem_raw;
        float* sinv = tptr + SINV_OFF;
        #pragma unroll
        for (int rg = 0; rg < 2; rg++) {
            const int rl0 = warp * 32 + rg * 16 + lr;   // local rows
            const int r0 = blockIdx.x * 128 + rl0;
            float ssA = 0.0f, ssB = 0.0f;
            #pragma unroll
            for (int b = 0; b < 8; b++) {
                const int col = 8 * b + 2 * lc;
                float2 y0 = h2f2(yc[rg][b][0]);
                float2 y1 = h2f2(yc[rg][b][1]);
                float2 x0 = *(const float2*)(xin + base + (size_t)r0 * DIM + col);
                float2 x1 = *(const float2*)(xin + base + (size_t)(r0 + 8) * DIM + col);
                float a0 = fmaxf(y0.x + x0.x, 0.0f), a1 = fmaxf(y0.y + x0.y, 0.0f);
                float b0 = fmaxf(y1.x + x1.x, 0.0f), b1 = fmaxf(y1.y + x1.y, 0.0f);
                ssA = fmaf(a0, a0, fmaf(a1, a1, ssA));
                ssB = fmaf(b0, b0, fmaf(b1, b1, ssB));
                tptr[rl0 * TILE_STRIDE + col]           = a0;
                tptr[rl0 * TILE_STRIDE + col + 1]       = a1;
                tptr[(rl0 + 8) * TILE_STRIDE + col]     = b0;
                tptr[(rl0 + 8) * TILE_STRIDE + col + 1] = b1;
            }
            ssA += __shfl_xor_sync(0xFFFFFFFFu, ssA, 1);
            ssA += __shfl_xor_sync(0xFFFFFFFFu, ssA, 2);
            ssB += __shfl_xor_sync(0xFFFFFFFFu, ssB, 1);
            ssB += __shfl_xor_sync(0xFFFFFFFFu, ssB, 2);
            if (lc == 0) {
                sinv[rl0]     = 1.0f / fmaxf(sqrtf(ssA), 1e-12f);
                sinv[rl0 + 8] = 1.0f / fmaxf(sqrtf(ssB), 1e-12f);
            }
        }
        __syncthreads();

        // y (f32), qn (f16), vt (f16 transposed)
        const size_t rbase = base + (size_t)blockIdx.x * 128 * DIM;
        #pragma unroll
        for (int i = 0; i < 32; i++) {
            int idx = tid + i * 128;          // 4096 float2
            int row = idx >> 5, s = idx & 31;
            float v0 = tptr[row * TILE_STRIDE + 2 * s];
            float v1 = tptr[row * TILE_STRIDE + 2 * s + 1];
            *(float2*)(yout + rbase + (size_t)row * DIM + 2 * s) = make_float2(v0, v1);
            float si = sinv[row];
            *(uint32_t*)(qn_out + rbase + (size_t)row * DIM + 2 * s) =
                packh(v0 * si, v1 * si);
        }
        __half* vb = vt_out + (size_t)blockIdx.y * NSEQ * DIM + blockIdx.x * 128;
        #pragma unroll
        for (int i = 0; i < 64; i++) {
            int idx = tid + i * 128;          // 8192 elements
            int d = idx >> 7, n = idx & 127;
            vb[(size_t)d * NSEQ + n] = __float2half(tptr[n * TILE_STRIDE + d]);
        }
    }
}

// ---------------------------------------------------------------------------
// Driver (graph-capturable)
// ---------------------------------------------------------------------------
extern "C" void kernel_launch(void* const* d_in, const int* in_sizes, int n_in,
                              void* d_out, int out_size) {
    const float* x      = (const float*)d_in[0];
    const float* W1     = (const float*)d_in[1];
    const float* W2     = (const float*)d_in[2];
    const float* alpha1 = (const float*)d_in[3];
    const float* alpha2 = (const float*)d_in[4];
    float* out = (float*)d_out;

    __half* qk1; cudaGetSymbolAddress((void**)&qk1, g_qk1);
    __half* vt1; cudaGetSymbolAddress((void**)&vt1, g_vt1);
    __half* qk2; cudaGetSymbolAddress((void**)&qk2, g_qk2);
    __half* vt2; cudaGetSymbolAddress((void**)&vt2, g_vt2);
    float* tmp;  cudaGetSymbolAddress((void**)&tmp, g_tmp);

    dim3 pgrid(NSEQ / 64, BH);
    dim3 agrid(NSEQ / 128, BH);

    prep_kernel<<<pgrid, 256>>>(x, qk1, vt1);
    attn_fused_kernel<1><<<agrid, 128>>>(qk1, vt1, W1, alpha1, x, tmp, qk2, vt2);
    attn_fused_kernel<0><<<agrid, 128>>>(qk2, vt2, W2, alpha2, tmp, out, nullptr, nullptr);
}